// round 3
// baseline (speedup 1.0000x reference)
#include <cuda_runtime.h>
#include <cuda_bf16.h>

// SparseLinear: out[b, c] = sum_l w[b,l] * table[x[b,l], c]
// B=4096, L=200, C=128, table = 1,000,000 x 128 fp32 (512 MB).
//
// L2-tiled persistent kernel: 4 table tiles of 256k rows (~75 MB unique
// referenced per tile, fits L2). A co-resident persistent grid processes one
// tile at a time, separated by a soft (timeout-protected, perf-only) grid
// barrier, so all repeat references to a row hit L2 while its tile is the
// active window. Per-CTA 64-bucket counting sort gives contiguous per-tile
// index segments (tile = bucket >> 4).

#define SL_L 200
#define SL_C 128
#define NBKT 64
#define BKT_SHIFT 14          // bucket = idx >> 14 (16384 rows / bucket)
#define NTILE 4               // tile = bucket >> 4  (= idx >> 18)
#define R_MAX 4               // max batch rows per CTA
#define CTAS_PER_SM 12

__device__ unsigned g_count = 0;
__device__ volatile unsigned g_sense = 0;

__device__ __forceinline__ void soft_grid_barrier(unsigned target, unsigned nctas)
{
    __syncthreads();
    if (threadIdx.x == 0) {
        unsigned old = atomicAdd(&g_count, 1u);
        if (old == nctas - 1u) {
            g_count = 0;                 // reset before release (others are spinning)
            __threadfence();
            atomicAdd((unsigned*)&g_sense, 1u);
        } else {
            // Perf-only barrier: bounded spin, never deadlocks.
            int spins = 0;
            while (g_sense < target && spins < 4000) { __nanosleep(100); ++spins; }
        }
    }
    __syncthreads();
}

__global__ __launch_bounds__(SL_C, CTAS_PER_SM) void sparse_linear_tiled(
    const int* __restrict__ x,
    const float* __restrict__ w,
    const float* __restrict__ table,
    float* __restrict__ out,
    int batch)
{
    __shared__ int   sxs[SL_L];              // staging (per row, reused)
    __shared__ float sws[SL_L];
    __shared__ int   sx2[R_MAX][SL_L];       // bucket-sorted indices per row
    __shared__ float sw2[R_MAX][SL_L];
    __shared__ int   off[NBKT];              // histogram / prefix / cursors
    __shared__ int   seg[R_MAX][NTILE + 1];  // per-row tile segment bounds

    const int t    = threadIdx.x;            // class column 0..127
    const int g    = blockIdx.x;
    const int grid = gridDim.x;

    // Snapshot the barrier sense before any barrier can complete this launch.
    const unsigned sense0 = g_sense;

    // Row assignment: rows g, g+grid, g+2*grid, ...
    int brow[R_MAX];
    int nrows = 0;
    #pragma unroll
    for (int r = 0; r < R_MAX; ++r) {
        int b = g + r * grid;
        brow[r] = (b < batch) ? b : -1;
        if (b < batch) nrows = r + 1;
    }

    // ---- Per-row counting sort into tile-contiguous order ----
    for (int r = 0; r < nrows; ++r) {
        const int b = brow[r];
        __syncthreads();
        if (t < NBKT) off[t] = 0;
        #pragma unroll
        for (int i = t; i < SL_L; i += SL_C) {
            sxs[i] = x[b * SL_L + i];
            sws[i] = w[b * SL_L + i];
        }
        __syncthreads();

        #pragma unroll
        for (int i = t; i < SL_L; i += SL_C)
            atomicAdd(&off[sxs[i] >> BKT_SHIFT], 1);
        __syncthreads();

        // Exclusive prefix over 64 counts (warp 0).
        if (t < 32) {
            const unsigned FULL = 0xffffffffu;
            int c0 = off[t], c1 = off[t + 32];
            int s0 = c0, s1 = c1;
            #pragma unroll
            for (int d = 1; d < 32; d <<= 1) {
                int n0 = __shfl_up_sync(FULL, s0, d);
                int n1 = __shfl_up_sync(FULL, s1, d);
                if (t >= d) { s0 += n0; s1 += n1; }
            }
            int tot0 = __shfl_sync(FULL, s0, 31);
            off[t]      = s0 - c0;
            off[t + 32] = tot0 + s1 - c1;
        }
        __syncthreads();

        // Record tile segment boundaries before scatter mutates the cursors.
        if (t <= NTILE) seg[r][t] = (t < NTILE) ? off[t * (NBKT / NTILE)] : SL_L;
        __syncthreads();

        #pragma unroll
        for (int i = t; i < SL_L; i += SL_C) {
            int   idx = sxs[i];
            float wv  = sws[i];
            int p = atomicAdd(&off[idx >> BKT_SHIFT], 1);
            sx2[r][p] = idx;
            sw2[r][p] = wv;
        }
    }
    __syncthreads();

    // ---- Tiled gather, paced by soft grid barriers ----
    float acc[R_MAX] = {0.0f, 0.0f, 0.0f, 0.0f};

    for (int tile = 0; tile < NTILE; ++tile) {
        for (int r = 0; r < nrows; ++r) {
            const int s = seg[r][tile];
            const int e = seg[r][tile + 1];
            float a = acc[r];
            #pragma unroll 4
            for (int l = s; l < e; ++l) {
                const unsigned o = (unsigned)sx2[r][l] * (unsigned)SL_C + (unsigned)t;
                a += sw2[r][l] * __ldg(table + o);
            }
            acc[r] = a;
        }
        if (tile < NTILE - 1)
            soft_grid_barrier(sense0 + (unsigned)tile + 1u, (unsigned)grid);
    }

    #pragma unroll
    for (int r = 0; r < R_MAX; ++r)
        if (brow[r] >= 0) out[brow[r] * SL_C + t] = acc[r];
}

extern "C" void kernel_launch(void* const* d_in, const int* in_sizes, int n_in,
                              void* d_out, int out_size)
{
    const int*   x     = (const int*)d_in[0];
    const float* w     = (const float*)d_in[1];
    const float* table = (const float*)d_in[2];
    float*       out   = (float*)d_out;

    const int batch = out_size / SL_C;   // 4096

    int dev = 0;
    cudaGetDevice(&dev);
    int sms = 148;
    cudaDeviceGetAttribute(&sms, cudaDevAttrMultiProcessorCount, dev);

    int grid = sms * CTAS_PER_SM;                       // co-resident persistent grid
    const int min_grid = (batch + R_MAX - 1) / R_MAX;   // coverage guard
    if (grid < min_grid) grid = min_grid;
    if (grid > batch) grid = batch;

    sparse_linear_tiled<<<grid, SL_C>>>(x, w, table, out, batch);
}

// round 5
// speedup vs baseline: 2.0840x; 2.0840x over previous
#include <cuda_runtime.h>

// SparseLinear: out[b, c] = sum_l w[b,l] * table[x[b,l], c]
// B=4096, L=200, C=128, table = 1,000,000 x 128 fp32 (512 MB).
//
// Warp-per-row vectorized gather: one LDG.128 warp-instruction fetches an
// entire 512 B table row (lane -> columns 4*lane..4*lane+3), so all 4 sectors
// of a row are requested together. The 4 warps of the CTA split the L
// dimension and 4-way reduce through shared memory. Per-CTA counting sort
// (64 buckets on idx>>14) keeps the gather stream address-ordered.

#define SL_L 200
#define SL_C 128
#define NBKT 64
#define BKT_SHIFT 14

__global__ __launch_bounds__(SL_C) void sparse_linear_kernel(
    const int* __restrict__ x,
    const float* __restrict__ w,
    const float* __restrict__ table,
    float* __restrict__ out)
{
    __shared__ int    sx[SL_L];
    __shared__ float  sw[SL_L];
    __shared__ int    sx2[SL_L];      // address-sorted
    __shared__ float  sw2[SL_L];
    __shared__ int    off[NBKT];
    __shared__ float4 sred[SL_C];     // 2 KB reduction buffer

    const int b    = blockIdx.x;
    const int t    = threadIdx.x;
    const int lane = t & 31;          // column group: cols 4*lane..4*lane+3
    const int wg   = t >> 5;          // warp id 0..3: handles l = wg, wg+4, ...

    if (t < NBKT) off[t] = 0;

    // Stage (x, w).
    #pragma unroll
    for (int i = t; i < SL_L; i += SL_C) {
        sx[i] = x[b * SL_L + i];
        sw[i] = w[b * SL_L + i];
    }
    __syncthreads();

    // Histogram by top bits.
    #pragma unroll
    for (int i = t; i < SL_L; i += SL_C)
        atomicAdd(&off[sx[i] >> BKT_SHIFT], 1);
    __syncthreads();

    // Exclusive prefix over 64 counts (warp 0).
    if (t < 32) {
        const unsigned FULL = 0xffffffffu;
        int c0 = off[t], c1 = off[t + 32];
        int s0 = c0, s1 = c1;
        #pragma unroll
        for (int d = 1; d < 32; d <<= 1) {
            int n0 = __shfl_up_sync(FULL, s0, d);
            int n1 = __shfl_up_sync(FULL, s1, d);
            if (t >= d) { s0 += n0; s1 += n1; }
        }
        int tot0 = __shfl_sync(FULL, s0, 31);
        off[t]      = s0 - c0;
        off[t + 32] = tot0 + s1 - c1;
    }
    __syncthreads();

    // Scatter into bucket-sorted order.
    #pragma unroll
    for (int i = t; i < SL_L; i += SL_C) {
        int   idx = sx[i];
        float wv  = sw[i];
        int p = atomicAdd(&off[idx >> BKT_SHIFT], 1);
        sx2[p] = idx;
        sw2[p] = wv;
    }
    __syncthreads();

    // Gather: warp wg covers l = wg, wg+4, ... (50 rows), one LDG.128 each.
    const float4* __restrict__ t4 = (const float4*)table;
    float4 acc = make_float4(0.f, 0.f, 0.f, 0.f);

    #pragma unroll 5
    for (int l = wg; l < SL_L; l += 4) {
        const unsigned o = (unsigned)sx2[l] * 32u + (unsigned)lane;
        const float  wv = sw2[l];
        const float4 v  = __ldg(t4 + o);
        acc.x += wv * v.x;
        acc.y += wv * v.y;
        acc.z += wv * v.z;
        acc.w += wv * v.w;
    }

    // 4-way reduce across warps, then warp 0 stores the row.
    sred[t] = acc;
    __syncthreads();

    if (wg == 0) {
        float4 a0 = sred[lane];
        float4 a1 = sred[lane + 32];
        float4 a2 = sred[lane + 64];
        float4 a3 = sred[lane + 96];
        float4 r;
        r.x = (a0.x + a1.x) + (a2.x + a3.x);
        r.y = (a0.y + a1.y) + (a2.y + a3.y);
        r.z = (a0.z + a1.z) + (a2.z + a3.z);
        r.w = (a0.w + a1.w) + (a2.w + a3.w);
        ((float4*)out)[b * 32 + lane] = r;
    }
}

extern "C" void kernel_launch(void* const* d_in, const int* in_sizes, int n_in,
                              void* d_out, int out_size)
{
    const int*   x     = (const int*)d_in[0];
    const float* w     = (const float*)d_in[1];
    const float* table = (const float*)d_in[2];
    float*       out   = (float*)d_out;

    int batch = out_size / SL_C;     // 4096
    if (batch <= 0) batch = 4096;
    sparse_linear_kernel<<<batch, SL_C>>>(x, w, table, out);
}